// round 15
// baseline (speedup 1.0000x reference)
#include <cuda_runtime.h>
#include <cuda_fp16.h>
#include <cstdint>

typedef uint32_t u32;

// Problem constants
#define Bk 2
#define Lk 2048
#define Sk 2048
#define Hk 8
#define Ek 64
#define Dk 64
#define NBH (Bk*Hk)

#define TQ 128            // queries per CTA
#define TS 64             // keys per chunk
#define NCHUNK (Sk/TS)    // 32
#define NTHREADS 256      // 8 warps; warp w owns q rows 16w..16w+15

// fp16 smem row strides (fp16 units)
#define KP2 72
#define VP2 72

// per-buffer tile block (halfs): KHI | KLO | VHI
#define B_KHI 0
#define B_KLO (TS*KP2)                 // 4608
#define B_VHI (2*TS*KP2)               // 9216
#define BUFSZ (2*TS*KP2 + TS*VP2)      // 13824 halfs
#define O_ST  (2*BUFSZ)                // 27648 halfs -> stats floats

// stats (float indices from O_ST)
#define S_DEN 0           // [128]
#define S_MX  128         // [128]
#define S_MXI 256         // [128]
#define S_INV 384         // [128]
#define S_KS  512         // [16][64]
#define S_KSUM 1536       // [64]
#define SMEM_BYTES (O_ST*2 + (S_KSUM + 64)*4)   // 61696 B

// Scratch
__device__ float g_Otmp[(size_t)NBH * Lk * Dk];
__device__ unsigned long long g_Key[NBH * Lk];

// fp16 mma m16n8k16: D += A*B (f32 accum)
__device__ __forceinline__ void mma16(float* d, u32 a0, u32 a1, u32 a2, u32 a3,
                                      u32 b0, u32 b1) {
    asm volatile(
        "mma.sync.aligned.m16n8k16.row.col.f32.f16.f16.f32 "
        "{%0,%1,%2,%3}, {%4,%5,%6,%7}, {%8,%9}, {%0,%1,%2,%3};"
        : "+f"(d[0]), "+f"(d[1]), "+f"(d[2]), "+f"(d[3])
        : "r"(a0), "r"(a1), "r"(a2), "r"(a3), "r"(b0), "r"(b1));
}

#define LDSM_X4(r0,r1,r2,r3,addr) \
    asm volatile("ldmatrix.sync.aligned.m8n8.x4.shared.b16 {%0,%1,%2,%3}, [%4];" \
        : "=r"(r0), "=r"(r1), "=r"(r2), "=r"(r3) : "r"(addr))
#define LDSM_X4T(r0,r1,r2,r3,addr) \
    asm volatile("ldmatrix.sync.aligned.m8n8.x4.trans.shared.b16 {%0,%1,%2,%3}, [%4];" \
        : "=r"(r0), "=r"(r1), "=r"(r2), "=r"(r3) : "r"(addr))

__device__ __forceinline__ u32 smem_u32(const void* p) {
    u32 a; asm("{ .reg .u64 t; cvta.to.shared.u64 t, %1; cvt.u32.u64 %0, t; }" : "=r"(a) : "l"(p));
    return a;
}

// RN split of a float pair into packed-half hi and lo fragments
__device__ __forceinline__ void split2(float x, float y, u32& hh, u32& ll) {
    __half2 h = __floats2half2_rn(x, y);
    float2 back = __half22float2(h);
    __half2 l = __floats2half2_rn(x - back.x, y - back.y);
    hh = *(u32*)&h; ll = *(u32*)&l;
}
__device__ __forceinline__ u32 pack2h(float x, float y) {
    __half2 h = __floats2half2_rn(x, y);
    return *(u32*)&h;
}

// load + split one K/V chunk into buffer `bb` (halfs offset), accumulating ksum
__device__ __forceinline__ void stage_chunk(__half* smh, int bb,
                                            const float* __restrict__ Kg,
                                            const float* __restrict__ Vg,
                                            int b, int h, int s0,
                                            int r0, int c0, float* ksum_r)
{
    #pragma unroll
    for (int i = 0; i < 4; i++) {
        int r = r0 + 16*i;
        float4 v = *(const float4*)(Kg + ((size_t)((b*Sk + s0 + r)*Hk + h))*Ek + c0);
        ksum_r[0] += v.x; ksum_r[1] += v.y; ksum_r[2] += v.z; ksum_r[3] += v.w;
        u32 h0, l0, h1, l1;
        split2(v.x, v.y, h0, l0);
        split2(v.z, v.w, h1, l1);
        *(uint2*)(smh + bb + B_KHI + r*KP2 + c0) = make_uint2(h0, h1);
        *(uint2*)(smh + bb + B_KLO + r*KP2 + c0) = make_uint2(l0, l1);
    }
    #pragma unroll
    for (int i = 0; i < 4; i++) {
        int r = r0 + 16*i;
        float4 v = *(const float4*)(Vg + ((size_t)((b*Sk + s0 + r)*Hk + h))*Dk + c0);
        *(uint2*)(smh + bb + B_VHI + r*VP2 + c0) =
            make_uint2(pack2h(v.x, v.y), pack2h(v.z, v.w));
    }
}

// ---------------------------------------------------------------------------
// Kernel 1: fp16-split flash attention; register Q frags and P; double-buffer.
// GEMM1 (3-term): Qhi.Khi + Qlo.Khi + Qhi.Klo ; GEMM2 (1-term): Phi.Vhi.
// Exact M_sp: mean via q.Ksum; max via approx-argmax + exact fp32 re-dot.
// ---------------------------------------------------------------------------
__global__ __launch_bounds__(NTHREADS, 2)
void k_attn(const float* __restrict__ Qg,
            const float* __restrict__ Kg,
            const float* __restrict__ Vg)
{
    extern __shared__ __half smh[];
    float* st = (float*)(smh + O_ST);
    const u32 sb = smem_u32(smh);

    const int tile = blockIdx.x & 15;
    const int bh   = blockIdx.x >> 4;
    const int b = bh >> 3, h = bh & 7;
    const int q0 = tile * TQ;
    const int tid  = threadIdx.x;
    const int lane = tid & 31, wid = tid >> 5;
    const int g = lane >> 2, tg = lane & 3;
    const int qr = wid << 4;             // warp's q-row base (16 rows)

    const int r0 = tid >> 4;             // 0..15 (K/V load row group)
    const int c0 = (tid & 15) << 2;      // 0..60

    // ldmatrix.x4 per-lane address components
    const int kRow4 = (lane & 7) + ((lane >> 4) << 3);   // K: s row (matrices 0,1 / 2,3)
    const int kCol4 = ((lane >> 3) & 1) << 3;            // K: e k-block (0 or 8)
    const int vRow4 = lane & 15;                         // V: s row
    const int vCol4 = (lane >> 4) << 3;                  // V: d col half

    // ---- build Q fragments in registers (once) ----
    u32 qh[4][4], ql[4][4];
    {
        const float* qbase = Qg + ((size_t)((b*Lk + q0 + qr)*Hk + h))*Ek;
        const int rs = Hk*Ek;            // row stride in floats
        #pragma unroll
        for (int ks = 0; ks < 4; ks++) {
            int e0 = 16*ks + 2*tg;
            float2 v0 = *(const float2*)(qbase + (size_t)g*rs     + e0);
            float2 v1 = *(const float2*)(qbase + (size_t)(g+8)*rs + e0);
            float2 v2 = *(const float2*)(qbase + (size_t)g*rs     + e0 + 8);
            float2 v3 = *(const float2*)(qbase + (size_t)(g+8)*rs + e0 + 8);
            split2(v0.x, v0.y, qh[ks][0], ql[ks][0]);
            split2(v1.x, v1.y, qh[ks][1], ql[ks][1]);
            split2(v2.x, v2.y, qh[ks][2], ql[ks][2]);
            split2(v3.x, v3.y, qh[ks][3], ql[ks][3]);
        }
    }

    float D2[8][4];
    #pragma unroll
    for (int nt = 0; nt < 8; nt++)
        #pragma unroll
        for (int r = 0; r < 4; r++) D2[nt][r] = 0.f;

    float den0 = 0.f, den1 = 0.f;
    float mx0 = -1e30f, mx1 = -1e30f;
    int   mi0 = 0, mi1 = 0;
    float ksum_r[4] = {0.f,0.f,0.f,0.f};

    // ---- prologue: stage chunk 0 into buffer 0 ----
    stage_chunk(smh, 0, Kg, Vg, b, h, 0, r0, c0, ksum_r);
    __syncthreads();

    for (int ch = 0; ch < NCHUNK; ch++) {
        const int s0 = ch * TS;
        const int cur = (ch & 1) * BUFSZ;

        // ---- stage next chunk into the other buffer ----
        if (ch + 1 < NCHUNK)
            stage_chunk(smh, BUFSZ - cur, Kg, Vg, b, h, s0 + TS, r0, c0, ksum_r);

        // ---- GEMM1: D1(16q x 64s) = Q.K^T, 3-term fp16 split ----
        float D1[8][4];
        #pragma unroll
        for (int nt = 0; nt < 8; nt++)
            #pragma unroll
            for (int r = 0; r < 4; r++) D1[nt][r] = 0.f;

        #pragma unroll
        for (int ks = 0; ks < 4; ks++) {
            const int e0 = ks << 4;
            #pragma unroll
            for (int nt2 = 0; nt2 < 4; nt2++) {
                const int scol = nt2 << 4;
                u32 bh0, bh1, bh2, bh3, bl0, bl1, bl2, bl3;
                LDSM_X4(bh0, bh1, bh2, bh3,
                        sb + 2*(cur + B_KHI + (scol + kRow4)*KP2 + e0 + kCol4));
                LDSM_X4(bl0, bl1, bl2, bl3,
                        sb + 2*(cur + B_KLO + (scol + kRow4)*KP2 + e0 + kCol4));
                mma16(D1[2*nt2  ], qh[ks][0], qh[ks][1], qh[ks][2], qh[ks][3], bh0, bh1);
                mma16(D1[2*nt2  ], ql[ks][0], ql[ks][1], ql[ks][2], ql[ks][3], bh0, bh1);
                mma16(D1[2*nt2  ], qh[ks][0], qh[ks][1], qh[ks][2], qh[ks][3], bl0, bl1);
                mma16(D1[2*nt2+1], qh[ks][0], qh[ks][1], qh[ks][2], qh[ks][3], bh2, bh3);
                mma16(D1[2*nt2+1], ql[ks][0], ql[ks][1], ql[ks][2], ql[ks][3], bh2, bh3);
                mma16(D1[2*nt2+1], qh[ks][0], qh[ks][1], qh[ks][2], qh[ks][3], bl2, bl3);
            }
        }

        // ---- softmax + argmax/den stats (in regs, fp32 exp) ----
        #pragma unroll
        for (int nt = 0; nt < 8; nt++) {
            const int sglob = s0 + (nt << 3) + 2*tg;
            float s00 = D1[nt][0], s01 = D1[nt][1];
            float s10 = D1[nt][2], s11 = D1[nt][3];
            float m0 = fmaxf(s00, s01), m1 = fmaxf(s10, s11);
            if (m0 > mx0) { mx0 = m0; mi0 = sglob + (s01 > s00); }
            if (m1 > mx1) { mx1 = m1; mi1 = sglob + (s11 > s10); }
            float p00 = __expf(s00 * 0.125f), p01 = __expf(s01 * 0.125f);
            float p10 = __expf(s10 * 0.125f), p11 = __expf(s11 * 0.125f);
            den0 += p00 + p01;
            den1 += p10 + p11;
            D1[nt][0] = p00; D1[nt][1] = p01; D1[nt][2] = p10; D1[nt][3] = p11;
        }

        // ---- pack P fragments from D1 (hi only, register-resident) ----
        u32 ph[4][4];
        #pragma unroll
        for (int j = 0; j < 4; j++) {
            ph[j][0] = pack2h(D1[2*j  ][0], D1[2*j  ][1]);
            ph[j][1] = pack2h(D1[2*j  ][2], D1[2*j  ][3]);
            ph[j][2] = pack2h(D1[2*j+1][0], D1[2*j+1][1]);
            ph[j][3] = pack2h(D1[2*j+1][2], D1[2*j+1][3]);
        }

        // ---- GEMM2: D2 += Phi . Vhi ----
        #pragma unroll
        for (int j = 0; j < 4; j++) {
            const int sb2 = j << 4;
            #pragma unroll
            for (int nt2 = 0; nt2 < 4; nt2++) {
                const int dcol = nt2 << 4;
                u32 v0, v1, v2, v3;
                LDSM_X4T(v0, v1, v2, v3,
                         sb + 2*(cur + B_VHI + (sb2 + vRow4)*VP2 + dcol + vCol4));
                mma16(D2[2*nt2  ], ph[j][0], ph[j][1], ph[j][2], ph[j][3], v0, v1);
                mma16(D2[2*nt2+1], ph[j][0], ph[j][1], ph[j][2], ph[j][3], v2, v3);
            }
        }

        __syncthreads();   // readers of buf `cur` done; stagers of other buf done
    }

    // ---- Ksum partials ----
    *(float4*)(st + S_KS + r0*64 + c0) =
        make_float4(ksum_r[0], ksum_r[1], ksum_r[2], ksum_r[3]);

    // ---- den/max/idx: reduce over the 4 tg lanes of each row ----
    {
        float d0 = den0, d1 = den1, m0 = mx0, m1 = mx1;
        int i0 = mi0, i1 = mi1;
        #pragma unroll
        for (int o = 1; o < 4; o <<= 1) {
            d0 += __shfl_xor_sync(0xffffffffu, d0, o);
            d1 += __shfl_xor_sync(0xffffffffu, d1, o);
            float om0 = __shfl_xor_sync(0xffffffffu, m0, o);
            int   oi0 = __shfl_xor_sync(0xffffffffu, i0, o);
            if (om0 > m0) { m0 = om0; i0 = oi0; }
            float om1 = __shfl_xor_sync(0xffffffffu, m1, o);
            int   oi1 = __shfl_xor_sync(0xffffffffu, i1, o);
            if (om1 > m1) { m1 = om1; i1 = oi1; }
        }
        if (tg == 0) {
            st[S_DEN + qr + g]     = d0;
            st[S_DEN + qr + g + 8] = d1;
            st[S_MX  + qr + g]     = m0;
            st[S_MX  + qr + g + 8] = m1;
            st[S_MXI + qr + g]     = __int_as_float(i0);
            st[S_MXI + qr + g + 8] = __int_as_float(i1);
        }
    }
    __syncthreads();

    if (tid < 64) {
        float s = 0.f;
        #pragma unroll
        for (int gr = 0; gr < 16; gr++) s += st[S_KS + gr*64 + tid];
        st[S_KSUM + tid] = s;
    }
    __syncthreads();

    // ---- exact M_sp per query (gmem Q/K dots) ----
    if (tid < TQ) {
        const int q = tid;
        st[S_INV + q] = 1.0f / st[S_DEN + q];
        int idx = __float_as_int(st[S_MXI + q]);
        const float* qrow = Qg + ((size_t)((b*Lk + q0 + q)*Hk + h))*Ek;
        const float* krow = Kg + ((size_t)((b*Sk + idx)*Hk + h))*Ek;
        float dot = 0.f, rs = 0.f;
        #pragma unroll 8
        for (int e = 0; e < Ek; e++) {
            float qv = qrow[e];
            dot = fmaf(qv, krow[e], dot);
            rs  = fmaf(qv, st[S_KSUM + e], rs);
        }
        float msp = dot - rs * (1.0f / (float)Sk);
        int bi = __float_as_int(msp);
        unsigned u = (unsigned)bi ^ ((bi < 0) ? 0xFFFFFFFFu : 0x80000000u);
        int l = q0 + q;
        g_Key[bh*Lk + l] = ((unsigned long long)u << 32) | (unsigned)(~l);
    }
    __syncthreads();

    // ---- epilogue: normalize + write Otmp ----
    float* dst = g_Otmp + ((size_t)bh * Lk + q0) * Dk;
    {
        float inv0 = st[S_INV + qr + g];
        float inv1 = st[S_INV + qr + g + 8];
        #pragma unroll
        for (int nt = 0; nt < 8; nt++) {
            const int dcol = (nt << 3) + 2*tg;
            *(float2*)(dst + (size_t)(qr+g  )*Dk + dcol) =
                make_float2(D2[nt][0]*inv0, D2[nt][1]*inv0);
            *(float2*)(dst + (size_t)(qr+g+8)*Dk + dcol) =
                make_float2(D2[nt][2]*inv1, D2[nt][3]*inv1);
        }
    }
}

// ---------------------------------------------------------------------------
// Kernel 2: rank + scatter. 128 CTAs (8 slices of 256 rows per bh); 512
// threads: 2 threads per row, each scans 1024 keys, combined via shfl.
// u64 keys with index tie-break (REQUIRED: fp32 M_sp collisions do occur).
// ---------------------------------------------------------------------------
#define RROWS 256
__global__ __launch_bounds__(512)
void k_rank_scatter(float* __restrict__ out)
{
    __shared__ unsigned long long sKey[Lk];
    __shared__ int sR[RROWS];
    const int slice = blockIdx.x & 7;
    const int bh    = blockIdx.x >> 3;
    const int b = bh >> 3, h = bh & 7;
    const int t = threadIdx.x;
    const int base = slice * RROWS;

    for (int i = t; i < Lk; i += 512)
        sKey[i] = g_Key[bh*Lk + i];
    __syncthreads();

    const int lrow = t >> 1;                // 0..255
    const int half = t & 1;
    const unsigned long long my = sKey[base + lrow];
    const int j0 = half * 1024;
    int c0 = 0, c1 = 0;
    #pragma unroll 4
    for (int j = j0; j < j0 + 1024; j += 2) {
        c0 += (sKey[j]   > my);
        c1 += (sKey[j+1] > my);
    }
    int cnt = c0 + c1;
    cnt += __shfl_xor_sync(0xffffffffu, cnt, 1);
    if (half == 0) sR[lrow] = cnt;
    __syncthreads();

    // Scatter: out[b, rank(l), h, :] = Otmp[bh, l, :]
    const float* src = g_Otmp + ((size_t)bh * Lk + base) * Dk;
    for (int w = t; w < RROWS * (Dk/4); w += 512) {
        int lr = w >> 4;
        int c  = (w & 15) * 4;
        float4 v = *(const float4*)(src + lr*Dk + c);
        int rr = sR[lr];
        *(float4*)(out + (((size_t)b*Lk + rr)*Hk + h)*Dk + c) = v;
    }
}

// ---------------------------------------------------------------------------
extern "C" void kernel_launch(void* const* d_in, const int* in_sizes, int n_in,
                              void* d_out, int out_size)
{
    (void)in_sizes; (void)n_in; (void)out_size;
    const float* Q = (const float*)d_in[0];
    const float* K = (const float*)d_in[1];
    const float* V = (const float*)d_in[2];
    float* out = (float*)d_out;

    cudaFuncSetAttribute(k_attn, cudaFuncAttributeMaxDynamicSharedMemorySize, SMEM_BYTES);

    k_attn<<<NBH * (Lk / TQ), NTHREADS, SMEM_BYTES>>>(Q, K, V);
    k_rank_scatter<<<NBH * 8, 512>>>(out);
}

// round 17
// speedup vs baseline: 1.0467x; 1.0467x over previous
#include <cuda_runtime.h>
#include <cuda_fp16.h>
#include <cstdint>

typedef uint32_t u32;

// Problem constants
#define Bk 2
#define Lk 2048
#define Sk 2048
#define Hk 8
#define Ek 64
#define Dk 64
#define NBH (Bk*Hk)

#define TQ 128            // queries per CTA
#define TS 64             // keys per chunk
#define NCHUNK (Sk/TS)    // 32
#define NTHREADS 256      // 8 warps; warp w owns q rows 16w..16w+15

// fp16 smem row strides (fp16 units)
#define KP2 72
#define VP2 72

// per-buffer tile block (halfs): KHI | KLO | VHI
#define B_KHI 0
#define B_KLO (TS*KP2)                 // 4608
#define B_VHI (2*TS*KP2)               // 9216
#define BUFSZ (2*TS*KP2 + TS*VP2)      // 13824 halfs
#define O_ST  (2*BUFSZ)                // 27648 halfs -> stats floats

// stats (float indices from O_ST)
#define S_DEN 0           // [128]
#define S_MX  128         // [128]
#define S_MXI 256         // [128]
#define S_INV 384         // [128]
#define S_KS  512         // [16][64]
#define S_KSUM 1536       // [64]
#define SMEM_BYTES (O_ST*2 + (S_KSUM + 64)*4)   // 61696 B

// Scratch
__device__ float g_Otmp[(size_t)NBH * Lk * Dk];
__device__ unsigned long long g_Key[NBH * Lk];

// fp16 mma m16n8k16: D += A*B (f32 accum)
__device__ __forceinline__ void mma16(float* d, u32 a0, u32 a1, u32 a2, u32 a3,
                                      u32 b0, u32 b1) {
    asm volatile(
        "mma.sync.aligned.m16n8k16.row.col.f32.f16.f16.f32 "
        "{%0,%1,%2,%3}, {%4,%5,%6,%7}, {%8,%9}, {%0,%1,%2,%3};"
        : "+f"(d[0]), "+f"(d[1]), "+f"(d[2]), "+f"(d[3])
        : "r"(a0), "r"(a1), "r"(a2), "r"(a3), "r"(b0), "r"(b1));
}

#define LDSM_X2(r0,r1,addr) \
    asm volatile("ldmatrix.sync.aligned.m8n8.x2.shared.b16 {%0,%1}, [%2];" \
        : "=r"(r0), "=r"(r1) : "r"(addr))
#define LDSM_X2T(r0,r1,addr) \
    asm volatile("ldmatrix.sync.aligned.m8n8.x2.trans.shared.b16 {%0,%1}, [%2];" \
        : "=r"(r0), "=r"(r1) : "r"(addr))

__device__ __forceinline__ u32 smem_u32(const void* p) {
    u32 a; asm("{ .reg .u64 t; cvta.to.shared.u64 t, %1; cvt.u32.u64 %0, t; }" : "=r"(a) : "l"(p));
    return a;
}

// RN split of a float pair into packed-half hi and lo fragments
__device__ __forceinline__ void split2(float x, float y, u32& hh, u32& ll) {
    __half2 h = __floats2half2_rn(x, y);
    float2 back = __half22float2(h);
    __half2 l = __floats2half2_rn(x - back.x, y - back.y);
    hh = *(u32*)&h; ll = *(u32*)&l;
}
__device__ __forceinline__ u32 pack2h(float x, float y) {
    __half2 h = __floats2half2_rn(x, y);
    return *(u32*)&h;
}

// load + split one K/V chunk into buffer `bb` (halfs offset), accumulating ksum
__device__ __forceinline__ void stage_chunk(__half* smh, int bb,
                                            const float* __restrict__ Kg,
                                            const float* __restrict__ Vg,
                                            int b, int h, int s0,
                                            int r0, int c0, float* ksum_r)
{
    #pragma unroll
    for (int i = 0; i < 4; i++) {
        int r = r0 + 16*i;
        float4 v = *(const float4*)(Kg + ((size_t)((b*Sk + s0 + r)*Hk + h))*Ek + c0);
        ksum_r[0] += v.x; ksum_r[1] += v.y; ksum_r[2] += v.z; ksum_r[3] += v.w;
        u32 h0, l0, h1, l1;
        split2(v.x, v.y, h0, l0);
        split2(v.z, v.w, h1, l1);
        *(uint2*)(smh + bb + B_KHI + r*KP2 + c0) = make_uint2(h0, h1);
        *(uint2*)(smh + bb + B_KLO + r*KP2 + c0) = make_uint2(l0, l1);
    }
    #pragma unroll
    for (int i = 0; i < 4; i++) {
        int r = r0 + 16*i;
        float4 v = *(const float4*)(Vg + ((size_t)((b*Sk + s0 + r)*Hk + h))*Dk + c0);
        *(uint2*)(smh + bb + B_VHI + r*VP2 + c0) =
            make_uint2(pack2h(v.x, v.y), pack2h(v.z, v.w));
    }
}

// ---------------------------------------------------------------------------
// Kernel 1: fp16-split flash attention; register Q frags and P; double-buffer.
// GEMM1 (3-term): Qhi.Khi + Qlo.Khi + Qhi.Klo ; GEMM2 (1-term): Phi.Vhi.
// Exact M_sp: mean via q.Ksum; max via approx-argmax + exact fp32 re-dot.
// ---------------------------------------------------------------------------
__global__ __launch_bounds__(NTHREADS, 2)
void k_attn(const float* __restrict__ Qg,
            const float* __restrict__ Kg,
            const float* __restrict__ Vg)
{
    extern __shared__ __half smh[];
    float* st = (float*)(smh + O_ST);
    const u32 sb = smem_u32(smh);

    const int tile = blockIdx.x & 15;
    const int bh   = blockIdx.x >> 4;
    const int b = bh >> 3, h = bh & 7;
    const int q0 = tile * TQ;
    const int tid  = threadIdx.x;
    const int lane = tid & 31, wid = tid >> 5;
    const int g = lane >> 2, tg = lane & 3;
    const int qr = wid << 4;             // warp's q-row base (16 rows)

    const int r0 = tid >> 4;             // 0..15 (K/V load row group)
    const int c0 = (tid & 15) << 2;      // 0..60

    // ldmatrix per-lane address components
    const int bRowK = lane & 7;          // K B-frag row (s within 8)
    const int bColK = lane & 8;          // K B-frag k-block (0 or 8)
    const int vRow  = lane & 15;         // V B-frag row (s within 16)

    // ---- build Q fragments in registers (once) ----
    u32 qh[4][4], ql[4][4];
    {
        const float* qbase = Qg + ((size_t)((b*Lk + q0 + qr)*Hk + h))*Ek;
        const int rs = Hk*Ek;            // row stride in floats
        #pragma unroll
        for (int ks = 0; ks < 4; ks++) {
            int e0 = 16*ks + 2*tg;
            float2 v0 = *(const float2*)(qbase + (size_t)g*rs     + e0);
            float2 v1 = *(const float2*)(qbase + (size_t)(g+8)*rs + e0);
            float2 v2 = *(const float2*)(qbase + (size_t)g*rs     + e0 + 8);
            float2 v3 = *(const float2*)(qbase + (size_t)(g+8)*rs + e0 + 8);
            split2(v0.x, v0.y, qh[ks][0], ql[ks][0]);
            split2(v1.x, v1.y, qh[ks][1], ql[ks][1]);
            split2(v2.x, v2.y, qh[ks][2], ql[ks][2]);
            split2(v3.x, v3.y, qh[ks][3], ql[ks][3]);
        }
    }

    float D2[8][4];
    #pragma unroll
    for (int nt = 0; nt < 8; nt++)
        #pragma unroll
        for (int r = 0; r < 4; r++) D2[nt][r] = 0.f;

    float den0 = 0.f, den1 = 0.f;
    float mx0 = -1e30f, mx1 = -1e30f;
    int   mi0 = 0, mi1 = 0;
    float ksum_r[4] = {0.f,0.f,0.f,0.f};

    // ---- prologue: stage chunk 0 into buffer 0 ----
    stage_chunk(smh, 0, Kg, Vg, b, h, 0, r0, c0, ksum_r);
    __syncthreads();

    for (int ch = 0; ch < NCHUNK; ch++) {
        const int s0 = ch * TS;
        const int cur = (ch & 1) * BUFSZ;

        // ---- stage next chunk into the other buffer ----
        if (ch + 1 < NCHUNK)
            stage_chunk(smh, BUFSZ - cur, Kg, Vg, b, h, s0 + TS, r0, c0, ksum_r);

        // ---- GEMM1: D1(16q x 64s) = Q.K^T, 3-term fp16 split ----
        float D1[8][4];
        #pragma unroll
        for (int nt = 0; nt < 8; nt++)
            #pragma unroll
            for (int r = 0; r < 4; r++) D1[nt][r] = 0.f;

        #pragma unroll
        for (int ks = 0; ks < 4; ks++) {
            const int e0 = ks << 4;
            #pragma unroll
            for (int nt = 0; nt < 8; nt++) {
                const int scol = nt << 3;
                u32 bh0, bh1, bl0, bl1;
                LDSM_X2(bh0, bh1, sb + 2*(cur + B_KHI + (scol + bRowK)*KP2 + e0 + bColK));
                LDSM_X2(bl0, bl1, sb + 2*(cur + B_KLO + (scol + bRowK)*KP2 + e0 + bColK));
                mma16(D1[nt], qh[ks][0], qh[ks][1], qh[ks][2], qh[ks][3], bh0, bh1);
                mma16(D1[nt], ql[ks][0], ql[ks][1], ql[ks][2], ql[ks][3], bh0, bh1);
                mma16(D1[nt], qh[ks][0], qh[ks][1], qh[ks][2], qh[ks][3], bl0, bl1);
            }
        }

        // ---- softmax + argmax/den stats (in regs) ----
        #pragma unroll
        for (int nt = 0; nt < 8; nt++) {
            const int sglob = s0 + (nt << 3) + 2*tg;
            float s00 = D1[nt][0], s01 = D1[nt][1];
            float s10 = D1[nt][2], s11 = D1[nt][3];
            float m0 = fmaxf(s00, s01), m1 = fmaxf(s10, s11);
            if (m0 > mx0) { mx0 = m0; mi0 = sglob + (s01 > s00); }
            if (m1 > mx1) { mx1 = m1; mi1 = sglob + (s11 > s10); }
            float p00 = __expf(s00 * 0.125f), p01 = __expf(s01 * 0.125f);
            float p10 = __expf(s10 * 0.125f), p11 = __expf(s11 * 0.125f);
            den0 += p00 + p01;
            den1 += p10 + p11;
            D1[nt][0] = p00; D1[nt][1] = p01; D1[nt][2] = p10; D1[nt][3] = p11;
        }

        // ---- pack P fragments from D1 (hi only, register-resident) ----
        u32 ph[4][4];
        #pragma unroll
        for (int j = 0; j < 4; j++) {
            ph[j][0] = pack2h(D1[2*j  ][0], D1[2*j  ][1]);
            ph[j][1] = pack2h(D1[2*j  ][2], D1[2*j  ][3]);
            ph[j][2] = pack2h(D1[2*j+1][0], D1[2*j+1][1]);
            ph[j][3] = pack2h(D1[2*j+1][2], D1[2*j+1][3]);
        }

        // ---- GEMM2: D2 += Phi . Vhi ----
        #pragma unroll
        for (int j = 0; j < 4; j++) {
            const int sb2 = j << 4;
            #pragma unroll
            for (int nt = 0; nt < 8; nt++) {
                const int dcol = nt << 3;
                u32 v0, v1;
                LDSM_X2T(v0, v1, sb + 2*(cur + B_VHI + (sb2 + vRow)*VP2 + dcol));
                mma16(D2[nt], ph[j][0], ph[j][1], ph[j][2], ph[j][3], v0, v1);
            }
        }

        __syncthreads();   // readers of buf `cur` done; stagers of other buf done
    }

    // ---- Ksum partials ----
    *(float4*)(st + S_KS + r0*64 + c0) =
        make_float4(ksum_r[0], ksum_r[1], ksum_r[2], ksum_r[3]);

    // ---- den/max/idx: reduce over the 4 tg lanes of each row ----
    {
        float d0 = den0, d1 = den1, m0 = mx0, m1 = mx1;
        int i0 = mi0, i1 = mi1;
        #pragma unroll
        for (int o = 1; o < 4; o <<= 1) {
            d0 += __shfl_xor_sync(0xffffffffu, d0, o);
            d1 += __shfl_xor_sync(0xffffffffu, d1, o);
            float om0 = __shfl_xor_sync(0xffffffffu, m0, o);
            int   oi0 = __shfl_xor_sync(0xffffffffu, i0, o);
            if (om0 > m0) { m0 = om0; i0 = oi0; }
            float om1 = __shfl_xor_sync(0xffffffffu, m1, o);
            int   oi1 = __shfl_xor_sync(0xffffffffu, i1, o);
            if (om1 > m1) { m1 = om1; i1 = oi1; }
        }
        if (tg == 0) {
            st[S_DEN + qr + g]     = d0;
            st[S_DEN + qr + g + 8] = d1;
            st[S_MX  + qr + g]     = m0;
            st[S_MX  + qr + g + 8] = m1;
            st[S_MXI + qr + g]     = __int_as_float(i0);
            st[S_MXI + qr + g + 8] = __int_as_float(i1);
        }
    }
    __syncthreads();

    if (tid < 64) {
        float s = 0.f;
        #pragma unroll
        for (int gr = 0; gr < 16; gr++) s += st[S_KS + gr*64 + tid];
        st[S_KSUM + tid] = s;
    }
    __syncthreads();

    // ---- exact M_sp per query (gmem Q/K dots) ----
    if (tid < TQ) {
        const int q = tid;
        st[S_INV + q] = 1.0f / st[S_DEN + q];
        int idx = __float_as_int(st[S_MXI + q]);
        const float* qrow = Qg + ((size_t)((b*Lk + q0 + q)*Hk + h))*Ek;
        const float* krow = Kg + ((size_t)((b*Sk + idx)*Hk + h))*Ek;
        float dot = 0.f, rs = 0.f;
        #pragma unroll 8
        for (int e = 0; e < Ek; e++) {
            float qv = qrow[e];
            dot = fmaf(qv, krow[e], dot);
            rs  = fmaf(qv, st[S_KSUM + e], rs);
        }
        float msp = dot - rs * (1.0f / (float)Sk);
        int bi = __float_as_int(msp);
        unsigned u = (unsigned)bi ^ ((bi < 0) ? 0xFFFFFFFFu : 0x80000000u);
        int l = q0 + q;
        g_Key[bh*Lk + l] = ((unsigned long long)u << 32) | (unsigned)(~l);
    }
    __syncthreads();

    // ---- epilogue: normalize + write Otmp ----
    float* dst = g_Otmp + ((size_t)bh * Lk + q0) * Dk;
    {
        float inv0 = st[S_INV + qr + g];
        float inv1 = st[S_INV + qr + g + 8];
        #pragma unroll
        for (int nt = 0; nt < 8; nt++) {
            const int dcol = (nt << 3) + 2*tg;
            *(float2*)(dst + (size_t)(qr+g  )*Dk + dcol) =
                make_float2(D2[nt][0]*inv0, D2[nt][1]*inv0);
            *(float2*)(dst + (size_t)(qr+g+8)*Dk + dcol) =
                make_float2(D2[nt][2]*inv1, D2[nt][3]*inv1);
        }
    }
}

// ---------------------------------------------------------------------------
// Kernel 2: rank + scatter. 128 CTAs (8 slices of 256 rows per bh); 1024
// threads: 4 threads per row. Thread quarter q scans keys j = 2q + 8i + {0,1}
// for i in [0,256): 4 quarters x 2 keys x 256 iters = all 2048 keys, with the
// 4 quarter-groups hitting 4 distinct 16B regions per iteration
// (conflict-free broadcast LDS.128). Combined via 2 shfls.
// ---------------------------------------------------------------------------
#define RROWS 256
__global__ __launch_bounds__(1024)
void k_rank_scatter(float* __restrict__ out)
{
    __shared__ unsigned long long sKey[Lk];
    __shared__ int sR[RROWS];
    const int slice = blockIdx.x & 7;
    const int bh    = blockIdx.x >> 3;
    const int b = bh >> 3, h = bh & 7;
    const int t = threadIdx.x;
    const int base = slice * RROWS;

    // load all 2048 keys: one ulonglong2 per thread
    ((ulonglong2*)sKey)[t] = ((const ulonglong2*)(g_Key + bh*Lk))[t];
    __syncthreads();

    const int lrow = t >> 2;                // 0..255
    const int qtr  = t & 3;
    const unsigned long long my = sKey[base + lrow];
    int c0 = 0, c1 = 0;
    #pragma unroll 4
    for (int i = 0; i < Lk/8; i++) {        // 256 iterations, 8 keys/iter/row
        ulonglong2 k2 = *(const ulonglong2*)(sKey + 2*qtr + 8*i);
        c0 += (k2.x > my);
        c1 += (k2.y > my);
    }
    int cnt = c0 + c1;
    cnt += __shfl_xor_sync(0xffffffffu, cnt, 1);
    cnt += __shfl_xor_sync(0xffffffffu, cnt, 2);
    if (qtr == 0) sR[lrow] = cnt;
    __syncthreads();

    // Scatter: out[b, rank(l), h, :] = Otmp[bh, l, :]
    const float* src = g_Otmp + ((size_t)bh * Lk + base) * Dk;
    for (int w = t; w < RROWS * (Dk/4); w += 1024) {
        int lr = w >> 4;
        int c  = (w & 15) * 4;
        float4 v = *(const float4*)(src + lr*Dk + c);
        int rr = sR[lr];
        *(float4*)(out + (((size_t)b*Lk + rr)*Hk + h)*Dk + c) = v;
    }
}

// ---------------------------------------------------------------------------
extern "C" void kernel_launch(void* const* d_in, const int* in_sizes, int n_in,
                              void* d_out, int out_size)
{
    (void)in_sizes; (void)n_in; (void)out_size;
    const float* Q = (const float*)d_in[0];
    const float* K = (const float*)d_in[1];
    const float* V = (const float*)d_in[2];
    float* out = (float*)d_out;

    cudaFuncSetAttribute(k_attn, cudaFuncAttributeMaxDynamicSharedMemorySize, SMEM_BYTES);

    k_attn<<<NBH * (Lk / TQ), NTHREADS, SMEM_BYTES>>>(Q, K, V);
    k_rank_scatter<<<NBH * 8, 1024>>>(out);
}